// round 1
// baseline (speedup 1.0000x reference)
#include <cuda_runtime.h>

#define C     62
#define FIN   512
#define FOUT  256
#define KCH   5
#define NCLS  2
#define BATCH 2048
#define REDN  (C*FIN)     // 31744
#define CFOUT (C*FOUT)    // 15872
#define NE    (C*C)       // 3844

// ---------------- scratch (device globals, no allocation) ----------------
__device__ float d_A[NE];                         // thresholded adjacency
__device__ float d_T[KCH*NE];                     // Chebyshev matrices T_k, row-major [c][i]
__device__ float d_G[NCLS*C*KCH*FOUT];            // [(n*62+i)*1280 + k*256 + f]
__device__ __align__(16) float d_Mf[REDN*NCLS];   // collapsed matrix, [(i*512+j)*2 + n]

// ---------------- 1) adjacency MLP + threshold ----------------
__global__ void k_adj(const float* __restrict__ coord, const float* __restrict__ w1,
                      const float* __restrict__ b1, const float* __restrict__ w2,
                      const float* __restrict__ b2) {
    int c1 = blockIdx.x;
    int c2 = threadIdx.x;
    if (c2 >= C) return;
    const float* cd = coord + (c1*C + c2)*4;
    float d0 = cd[0], d1 = cd[1], d2 = cd[2], d3 = cd[3];
    float acc = b2[0];
    #pragma unroll 8
    for (int h = 0; h < 64; h++) {
        float t = d0*w1[h] + d1*w1[64+h] + d2*w1[128+h] + d3*w1[192+h] + b1[h];
        t = fmaxf(t, 0.0f);
        acc += t * w2[h];
    }
    float v = (c1 != c2 && acc > 0.1f) ? acc : 0.0f;
    d_A[c1*C + c2] = v;
}

// ---------------- 2) Laplacian + Chebyshev polynomial matrices ----------------
__global__ void k_cheb() {
    __shared__ float Ls[NE];
    __shared__ float Ta[NE];
    __shared__ float Tb[NE];
    __shared__ float dis[C];
    int tid = threadIdx.x;   // 1024 threads

    for (int e = tid; e < NE; e += 1024) Ls[e] = d_A[e];
    __syncthreads();
    if (tid < C) {
        float s = 0.0f;
        #pragma unroll
        for (int j = 0; j < C; j++) s += Ls[tid*C + j];
        dis[tid] = (s > 0.0f) ? (1.0f / sqrtf(s)) : 0.0f;
    }
    __syncthreads();
    for (int e = tid; e < NE; e += 1024) {
        int r = e / C, c = e % C;
        float L = -(dis[r] * Ls[e] * dis[c]);
        Ls[e] = L;
        Ta[e] = L;                               // T1
        float t0 = (r == c) ? 1.0f : 0.0f;       // T0 = I
        Tb[e] = t0;
        d_T[0*NE + e] = t0;
        d_T[1*NE + e] = L;
    }
    __syncthreads();
    for (int k = 2; k < KCH; k++) {
        float v[4];
        int cnt = 0;
        for (int e = tid; e < NE; e += 1024, cnt++) {
            int r = e / C, c = e % C;
            float s = 0.0f;
            #pragma unroll
            for (int j = 0; j < C; j++) s += Ls[r*C + j] * Ta[j*C + c];
            v[cnt] = 2.0f*s - Tb[e];
        }
        __syncthreads();
        cnt = 0;
        for (int e = tid; e < NE; e += 1024, cnt++) {
            Tb[e] = Ta[e];
            Ta[e] = v[cnt];
            d_T[k*NE + e] = v[cnt];
        }
        __syncthreads();
    }
}

// ---------------- 3) G[n,i,k,f] = sum_c T_k[c,i] * fc_w[(c*256+f)*2+n] ----------------
__global__ void k_G(const float* __restrict__ fcw) {
    int g = blockIdx.x*blockDim.x + threadIdx.x;
    if (g >= NCLS*C*KCH*FOUT) return;
    int f  = g & 255;
    int k  = (g >> 8) % KCH;
    int ni = g / (KCH*FOUT);
    int i  = ni % C;
    int n  = ni / C;
    const float* T = d_T + k*NE;
    float acc = 0.0f;
    for (int c = 0; c < C; c++)
        acc += T[c*C + i] * fcw[(c*FOUT + f)*NCLS + n];
    d_G[g] = acc;
}

// ---------------- 4) zero the collapsed matrix ----------------
__global__ void k_zero() {
    int idx = blockIdx.x*blockDim.x + threadIdx.x;
    float4* p = (float4*)d_Mf;
    if (idx < (REDN*NCLS)/4) p[idx] = make_float4(0.f, 0.f, 0.f, 0.f);
}

// ---------------- 5) M[n,i,j] += conv_w * sum_{k,f} G[n,i,kf] * chebW[k,j,f] ----------
// GEMM M=124(ni) N=512(j) K=1280(kf), K split into 20 chunks of 64 across blockIdx.x
__global__ void __launch_bounds__(256) k_M(const float* __restrict__ chebW,
                                           const float* __restrict__ convw) {
    __shared__ float Gs[64*68];   // Gs[kk][r],  r = local row (i), padded stride 68
    __shared__ float Ws[64*68];   // Ws[kk][j]
    int tid = threadIdx.x;
    int kf0 = blockIdx.x * 64;    // never straddles a k boundary (256 % 64 == 0)
    int k   = kf0 >> 8;
    int f0  = kf0 & 255;
    int j0  = blockIdx.y * 64;
    int n   = blockIdx.z;

    {
        int cc = tid & 63;        // kk within chunk
        int r0 = tid >> 6;        // 0..3
        #pragma unroll
        for (int s = 0; s < 16; s++) {
            int r = r0 + s*4;
            float v = (r < C) ? d_G[(n*C + r)*(KCH*FOUT) + kf0 + cc] : 0.0f;
            Gs[cc*68 + r] = v;
        }
        #pragma unroll
        for (int s = 0; s < 16; s++) {
            int j = r0 + s*4;
            Ws[cc*68 + j] = chebW[k*(FIN*FOUT) + (j0 + j)*FOUT + f0 + cc];
        }
    }
    __syncthreads();

    int tx = tid & 15, ty = tid >> 4;
    int r4 = ty*4, j4 = tx*4;
    float acc[4][4] = {};
    #pragma unroll
    for (int kk = 0; kk < 64; kk++) {
        float4 g = *(const float4*)&Gs[kk*68 + r4];
        float4 w = *(const float4*)&Ws[kk*68 + j4];
        float gg[4] = {g.x, g.y, g.z, g.w};
        float ww[4] = {w.x, w.y, w.z, w.w};
        #pragma unroll
        for (int a = 0; a < 4; a++)
            #pragma unroll
            for (int b = 0; b < 4; b++)
                acc[a][b] += gg[a]*ww[b];
    }

    float cw = convw[0];
    #pragma unroll
    for (int a = 0; a < 4; a++) {
        int i = r4 + a;
        if (i >= C) continue;
        #pragma unroll
        for (int b = 0; b < 4; b++) {
            int j = j0 + j4 + b;
            atomicAdd(&d_Mf[(i*FIN + j)*NCLS + n], cw*acc[a][b]);
        }
    }
}

// ---------------- 6) constant term + initialize d_out ----------------
// const[n] = conv_w * sum_{c,f} cheb_b[f]*fc_w[cf,n] + conv_b * sum_cf fc_w[cf,n] + fc_b[n]
__global__ void k_const_out(const float* __restrict__ fcw, const float* __restrict__ chebb,
                            const float* __restrict__ convw, const float* __restrict__ convb,
                            const float* __restrict__ fcb, float* __restrict__ out) {
    __shared__ float red[1024];
    __shared__ float cst[2];
    int tid = threadIdx.x;   // 256
    float s0 = 0.f, s1 = 0.f, t0 = 0.f, t1 = 0.f;
    for (int cf = tid; cf < CFOUT; cf += 256) {
        float w0 = fcw[cf*2], w1 = fcw[cf*2 + 1];
        float bb = chebb[cf & 255];
        s0 += w0; s1 += w1; t0 += bb*w0; t1 += bb*w1;
    }
    red[tid] = s0; red[256+tid] = s1; red[512+tid] = t0; red[768+tid] = t1;
    __syncthreads();
    for (int off = 128; off > 0; off >>= 1) {
        if (tid < off) {
            red[tid]       += red[tid+off];
            red[256+tid]   += red[256+tid+off];
            red[512+tid]   += red[512+tid+off];
            red[768+tid]   += red[768+tid+off];
        }
        __syncthreads();
    }
    if (tid == 0) {
        float cw = convw[0], cb = convb[0];
        cst[0] = cw*red[512] + cb*red[0]   + fcb[0];
        cst[1] = cw*red[768] + cb*red[256] + fcb[1];
    }
    __syncthreads();
    float c0 = cst[0], c1 = cst[1];
    for (int b = tid; b < BATCH; b += 256) {
        out[b*2]     = c0;
        out[b*2 + 1] = c1;
    }
}

// ---------------- 7) main pass: final[b,n] += sum_idx x[b,idx]*M[idx,n] --------------
// 8 reduction chunks of 3968 x 128 batch-groups of 16. M chunk (31.7KB) in smem.
__global__ void __launch_bounds__(256) k_main(const float* __restrict__ x,
                                              float* __restrict__ out) {
    __shared__ __align__(16) float Ms[7936];
    int chunk = blockIdx.x & 7;
    int bg    = blockIdx.x >> 3;
    int idx0  = chunk * 3968;
    int tid   = threadIdx.x;

    const float4* Mf4 = (const float4*)(d_Mf + idx0*2);
    float4* Ms4 = (float4*)Ms;
    for (int t = tid; t < 1984; t += 256) Ms4[t] = Mf4[t];
    __syncthreads();

    int warp = tid >> 5, lane = tid & 31;
    int b0 = bg*16 + warp*2;
    const float4* xa = (const float4*)(x + (size_t)b0*REDN + idx0);
    const float4* xb = (const float4*)(x + (size_t)(b0+1)*REDN + idx0);

    float a0 = 0.f, a1 = 0.f, c0 = 0.f, c1 = 0.f;
    for (int t = lane; t < 992; t += 32) {
        float4 xv = xa[t];
        float4 yv = xb[t];
        float4 q0 = Ms4[2*t];
        float4 q1 = Ms4[2*t + 1];
        a0 += xv.x*q0.x + xv.y*q0.z + xv.z*q1.x + xv.w*q1.z;
        a1 += xv.x*q0.y + xv.y*q0.w + xv.z*q1.y + xv.w*q1.w;
        c0 += yv.x*q0.x + yv.y*q0.z + yv.z*q1.x + yv.w*q1.z;
        c1 += yv.x*q0.y + yv.y*q0.w + yv.z*q1.y + yv.w*q1.w;
    }
    #pragma unroll
    for (int off = 16; off; off >>= 1) {
        a0 += __shfl_down_sync(0xFFFFFFFFu, a0, off);
        a1 += __shfl_down_sync(0xFFFFFFFFu, a1, off);
        c0 += __shfl_down_sync(0xFFFFFFFFu, c0, off);
        c1 += __shfl_down_sync(0xFFFFFFFFu, c1, off);
    }
    if (lane == 0) {
        atomicAdd(&out[b0*2],       a0);
        atomicAdd(&out[b0*2 + 1],   a1);
        atomicAdd(&out[(b0+1)*2],   c0);
        atomicAdd(&out[(b0+1)*2+1], c1);
    }
}

// ---------------- launcher ----------------
extern "C" void kernel_launch(void* const* d_in, const int* in_sizes, int n_in,
                              void* d_out, int out_size) {
    const float* x      = (const float*)d_in[0];
    const float* coord  = (const float*)d_in[1];
    const float* adj_w1 = (const float*)d_in[2];
    const float* adj_b1 = (const float*)d_in[3];
    const float* adj_w2 = (const float*)d_in[4];
    const float* adj_b2 = (const float*)d_in[5];
    const float* cheb_W = (const float*)d_in[6];
    const float* cheb_b = (const float*)d_in[7];
    const float* conv_w = (const float*)d_in[8];
    const float* conv_b = (const float*)d_in[9];
    const float* fc_w   = (const float*)d_in[10];
    const float* fc_b   = (const float*)d_in[11];
    float* out = (float*)d_out;

    k_zero<<<(REDN*NCLS/4 + 255)/256, 256>>>();
    k_adj<<<C, 64>>>(coord, adj_w1, adj_b1, adj_w2, adj_b2);
    k_cheb<<<1, 1024>>>();
    k_G<<<(NCLS*C*KCH*FOUT + 255)/256, 256>>>(fc_w);
    dim3 gM(20, 8, 2);
    k_M<<<gM, 256>>>(cheb_W, conv_w);
    k_const_out<<<1, 256>>>(fc_w, cheb_b, conv_w, conv_b, fc_b, out);
    k_main<<<1024, 256>>>(x, out);
}